// round 5
// baseline (speedup 1.0000x reference)
#include <cuda_runtime.h>

// Problem constants
#define B       8
#define C       64
#define G       8
#define FPG     8
#define OCPG    8
#define REPD    32
#define H       256
#define Wd      256
#define PLANE   (H * Wd)             // 65536
#define PLANE4  (PLANE / 4)          // 16384
#define NWTS    (OCPG * 9)           // 72

// Tile: full image width x 16 rows; 512-thread blocks
#define TY      16
#define NTHR    512
#define SROWS   (TY + 2)             // 18
#define SSTR    260                  // floats per smem row (16B aligned)
#define SSTR4   (SSTR / 4)

// ---------------------------------------------------------------------------
// Fused kernel: weight-gen + channel-sum (reflect pad) + 3x3 dynamic conv.
// grid: (H/TY, B*G), block 512.
// Phase 2: thread = (x-quad q, output channel oc), 16 rows sliding window.
// ---------------------------------------------------------------------------
__global__ __launch_bounds__(NTHR, 3)
void dyn_conv(const float* __restrict__ x,
              const float* __restrict__ rep,
              const float* __restrict__ Wm,
              float* __restrict__ out) {
    const int bg = blockIdx.y;
    const int b  = bg >> 3;
    const int g  = bg & 7;
    const int y0 = blockIdx.x * TY;
    const int t  = threadIdx.x;

    __shared__ __align__(16) float S[SROWS * SSTR];
    __shared__ float wsh[NWTS];
    __shared__ float rsh[REPD];

    // ---- weight generation (tiny; W is L2-resident) ----
    if (t < REPD) rsh[t] = rep[b * REPD + t];
    __syncthreads();
    if (t < NWTS) {
        const float* wrow = Wm + (size_t)(g * NWTS + t) * REPD;
        float acc = 0.f;
#pragma unroll
        for (int j = 0; j < REPD; ++j) acc = fmaf(rsh[j], wrow[j], acc);
        wsh[t] = acc > 0.f ? acc : 0.1f * acc;
    }

    // ---- Phase 1: channel-sum 18 full-width rows into smem (all float4) ----
    const float4* xb = (const float4*)x + ((size_t)(b * C + g * FPG)) * PLANE4;
#pragma unroll
    for (int idx = t; idx < SROWS * 64; idx += NTHR) {   // 1152 float4s
        const int r  = idx >> 6;
        const int q4 = idx & 63;
        int yy = y0 - 1 + r;
        yy = (yy < 0) ? -yy : yy;
        yy = (yy >= H) ? (2 * H - 2 - yy) : yy;
        const float4* p = xb + (size_t)yy * 64 + q4;
        float4 s = p[0];
#pragma unroll
        for (int ch = 1; ch < FPG; ++ch) {
            const float4 v = p[(size_t)ch * PLANE4];
            s.x += v.x; s.y += v.y; s.z += v.z; s.w += v.w;
        }
        ((float4*)S)[r * SSTR4 + q4] = s;
    }
    __syncthreads();

    // ---- Phase 2: 3x3 conv, 1 output channel per thread, 16 rows ----
    const int q  = t & 63;            // x-quad: output cols 4q..4q+3
    const int oc = t >> 6;            // 0..7

    float w[9];
#pragma unroll
    for (int k = 0; k < 9; ++k) w[k] = wsh[oc * 9 + k];

    // reflect-remapped edge-tap columns
    const int cL = (q == 0)  ? 1   : 4 * q - 1;
    const int cR = (q == 63) ? 254 : 4 * q + 4;

    float4* o = (float4*)(out + ((size_t)(b * C + g * OCPG + oc)) * PLANE
                              + (size_t)y0 * Wd) + q;

    // sliding 6-wide window rows: a = top, m = mid
    float a0,a1,a2,a3,a4,a5, m0,m1,m2,m3,m4,m5;
    {
        const float4 v = *(const float4*)&S[0 * SSTR + 4 * q];
        a0 = S[0 * SSTR + cL]; a1 = v.x; a2 = v.y; a3 = v.z; a4 = v.w; a5 = S[0 * SSTR + cR];
    }
    {
        const float4 v = *(const float4*)&S[1 * SSTR + 4 * q];
        m0 = S[1 * SSTR + cL]; m1 = v.x; m2 = v.y; m3 = v.z; m4 = v.w; m5 = S[1 * SSTR + cR];
    }

#pragma unroll
    for (int r = 0; r < TY; ++r) {
        const float4 v = *(const float4*)&S[(r + 2) * SSTR + 4 * q];
        const float c0 = S[(r + 2) * SSTR + cL];
        const float c1 = v.x, c2 = v.y, c3 = v.z, c4 = v.w;
        const float c5 = S[(r + 2) * SSTR + cR];

        float4 u;
        u.x =      w[0]*a0;
        u.x = fmaf(w[1],a1,u.x);
        u.x = fmaf(w[2],a2,u.x);
        u.x = fmaf(w[3],m0,u.x);
        u.x = fmaf(w[4],m1,u.x);
        u.x = fmaf(w[5],m2,u.x);
        u.x = fmaf(w[6],c0,u.x);
        u.x = fmaf(w[7],c1,u.x);
        u.x = fmaf(w[8],c2,u.x);

        u.y =      w[0]*a1;
        u.y = fmaf(w[1],a2,u.y);
        u.y = fmaf(w[2],a3,u.y);
        u.y = fmaf(w[3],m1,u.y);
        u.y = fmaf(w[4],m2,u.y);
        u.y = fmaf(w[5],m3,u.y);
        u.y = fmaf(w[6],c1,u.y);
        u.y = fmaf(w[7],c2,u.y);
        u.y = fmaf(w[8],c3,u.y);

        u.z =      w[0]*a2;
        u.z = fmaf(w[1],a3,u.z);
        u.z = fmaf(w[2],a4,u.z);
        u.z = fmaf(w[3],m2,u.z);
        u.z = fmaf(w[4],m3,u.z);
        u.z = fmaf(w[5],m4,u.z);
        u.z = fmaf(w[6],c2,u.z);
        u.z = fmaf(w[7],c3,u.z);
        u.z = fmaf(w[8],c4,u.z);

        u.w =      w[0]*a3;
        u.w = fmaf(w[1],a4,u.w);
        u.w = fmaf(w[2],a5,u.w);
        u.w = fmaf(w[3],m3,u.w);
        u.w = fmaf(w[4],m4,u.w);
        u.w = fmaf(w[5],m5,u.w);
        u.w = fmaf(w[6],c3,u.w);
        u.w = fmaf(w[7],c4,u.w);
        u.w = fmaf(w[8],c5,u.w);

        o[(size_t)r * 64] = u;

        a0=m0; a1=m1; a2=m2; a3=m3; a4=m4; a5=m5;
        m0=c0; m1=c1; m2=c2; m3=c3; m4=c4; m5=c5;
    }
}

// ---------------------------------------------------------------------------
extern "C" void kernel_launch(void* const* d_in, const int* in_sizes, int n_in,
                              void* d_out, int out_size) {
    const float* x   = (const float*)d_in[0];
    const float* rep = (const float*)d_in[1];
    const float* Wm  = (const float*)d_in[2];
    float* out = (float*)d_out;

    dim3 grid(H / TY, B * G);
    dyn_conv<<<grid, NTHR>>>(x, rep, Wm, out);
}